// round 15
// baseline (speedup 1.0000x reference)
#include <cuda_runtime.h>
#include <cuda_fp16.h>
#include <cstdint>
#include <math.h>

// Problem constants
constexpr int B_ = 4, S_ = 2048, E_ = 1024, H_ = 16, D_ = 64;
constexpr int M_ = B_ * S_;            // 8192 rows
constexpr int NKQV = 3 * E_;           // 3072

// ---------------------------------------------------------------------------
// Scratch (device globals; pure fp16)
// ---------------------------------------------------------------------------
__device__ __half g_xh[(size_t)M_ * E_];
__device__ __half g_wkh[(size_t)NKQV * E_];
__device__ __half g_wph[(size_t)E_ * E_];
__device__ __half g_qh[(size_t)B_*H_*S_*D_];
__device__ __half g_kh[(size_t)B_*H_*S_*D_];
__device__ __half g_vth[(size_t)B_*H_*S_*D_];    // V stored transposed [bh][d][s]
__device__ __half g_yh[(size_t)M_ * E_];

// ---------------------------------------------------------------------------
// helpers
// ---------------------------------------------------------------------------
__device__ __forceinline__ uint32_t pack_f16x2(float a, float b) {
    __half2 h = __floats2half2_rn(a, b);
    return *(uint32_t*)&h;
}

__device__ __forceinline__ void mma16816h(float* c, const uint32_t* a,
                                          uint32_t b0, uint32_t b1) {
    asm volatile(
        "mma.sync.aligned.m16n8k16.row.col.f32.f16.f16.f32 "
        "{%0,%1,%2,%3}, {%4,%5,%6,%7}, {%8,%9}, {%0,%1,%2,%3};"
        : "+f"(c[0]), "+f"(c[1]), "+f"(c[2]), "+f"(c[3])
        : "r"(a[0]), "r"(a[1]), "r"(a[2]), "r"(a[3]), "r"(b0), "r"(b1));
}

__device__ __forceinline__ void ldsm_x4(uint32_t* r, uint32_t addr) {
    asm volatile(
        "ldmatrix.sync.aligned.m8n8.x4.shared.b16 {%0,%1,%2,%3}, [%4];"
        : "=r"(r[0]), "=r"(r[1]), "=r"(r[2]), "=r"(r[3]) : "r"(addr));
}

__device__ __forceinline__ uint32_t smem_u32(const void* p) {
    uint32_t a;
    asm("{ .reg .u64 t; cvta.to.shared.u64 t, %1; cvt.u32.u64 %0, t; }"
        : "=r"(a) : "l"(p));
    return a;
}
__device__ __forceinline__ void cp16(uint32_t dst, const void* src) {
    asm volatile("cp.async.ca.shared.global [%0], [%1], 16;"
                 :: "r"(dst), "l"(src));
}
#define CP_COMMIT() asm volatile("cp.async.commit_group;" ::: "memory")
#define CP_WAIT1()  asm volatile("cp.async.wait_group 1;" ::: "memory")
#define CP_WAIT0()  asm volatile("cp.async.wait_group 0;" ::: "memory")

// FMA-pipe exp2 (input in log2 units). ~2e-6 rel err.
__device__ __forceinline__ float exp2p(float x) {
    x = fmaxf(x, -80.f);
    float t = x + 12582912.f;
    int n = __float_as_int(t) - 0x4B400000;
    float r = x - (t - 12582912.f);
    float p = 1.33335581e-3f;
    p = fmaf(p, r, 9.61812911e-3f);
    p = fmaf(p, r, 5.55041087e-2f);
    p = fmaf(p, r, 2.40226507e-1f);
    p = fmaf(p, r, 6.93147180e-1f);
    p = fmaf(p, r, 1.0f);
    return p * __int_as_float((n + 127) << 23);
}

constexpr float QSCALE = 0.125f * 1.44269504088896340736f;

// ---------------------------------------------------------------------------
// conversion: fp32 -> fp16
// ---------------------------------------------------------------------------
__global__ void convH_kernel(const float* __restrict__ src,
                             __half* __restrict__ hi, int n4) {
    int i = blockIdx.x * blockDim.x + threadIdx.x;
    if (i >= n4) return;
    float4 v = ((const float4*)src)[i];
    ((uint2*)hi)[i] = make_uint2(pack_f16x2(v.x, v.y), pack_f16x2(v.z, v.w));
}

// ---------------------------------------------------------------------------
// GEMM (pure fp16, single MMA; R13 BK=32 config): C = Ah @ Bh^T + bias.
// 128x128x32 tiles, 4 warps of 64x64, 128 threads, 2-stage, 2 CTAs/SM.
// MODE 0: fp32 out. MODE 1: scatter q/k (natural), v (transposed).
// ---------------------------------------------------------------------------
constexpr int GBK = 32;
constexpr int GSTR = 40;
constexpr int GTILE_E = 128 * GSTR;          // 5120
constexpr int PSTAGE_E = 2 * GTILE_E;        // Ah, Bh
constexpr int PSMEM = 2 * PSTAGE_E * 2;      // 40960 B -> 2 CTAs/SM

template <int MODE>
__global__ __launch_bounds__(128, 2) void gemm_h1(
    const __half* __restrict__ Ah, const __half* __restrict__ Bh,
    const float* __restrict__ bias, float* __restrict__ C, int N, int K)
{
    extern __shared__ __half smh[];
    const uint32_t smb_u = smem_u32(smh);
    const int tid = threadIdx.x;
    const int lane = tid & 31;
    const int w = tid >> 5;
    const int wm = w & 1, wn = w >> 1;
    const int g = lane >> 2, t = lane & 3;
    const int m0 = blockIdx.y * 128;
    const int n0 = blockIdx.x * 128;

    const __half* bases[2] = { Ah + (size_t)m0 * K, Bh + (size_t)n0 * K };

    const int nsteps = K / GBK;

    auto issue = [&](int s) {
        __half* st = smh + (s & 1) * PSTAGE_E;
        const int k0 = s * GBK;
#pragma unroll
        for (int c = 0; c < 8; c++) {
            int ci = tid + c * 128;
            int arr = ci >> 9;
            int idx = ci & 511;
            int r = idx >> 2, ch = idx & 3;
            cp16(smem_u32(st + arr * GTILE_E + r * GSTR + ch * 8),
                 bases[arr] + (size_t)r * K + k0 + ch * 8);
        }
        CP_COMMIT();
    };

    const uint32_t a_off =
        (uint32_t)((wm * 64 + (lane & 15)) * GSTR + (lane >> 4) * 8) * 2;
    const uint32_t b_off =
        (uint32_t)((wn * 64 + ((lane >> 4) & 1) * 8 + (lane & 7)) * GSTR +
                   ((lane >> 3) & 1) * 8) * 2;

    float acc[4][8][4];
#pragma unroll
    for (int i = 0; i < 4; i++)
#pragma unroll
        for (int j = 0; j < 8; j++)
#pragma unroll
            for (int e = 0; e < 4; e++) acc[i][j][e] = 0.f;

    issue(0);
    issue(1);

    for (int s = 0; s < nsteps; s++) {
        if (s + 1 < nsteps) { CP_WAIT1(); } else { CP_WAIT0(); }
        __syncthreads();

        const uint32_t st = smb_u + (uint32_t)((s & 1) * PSTAGE_E) * 2;
        const uint32_t uAh = st;
        const uint32_t uBh = st + GTILE_E * 2;

#pragma unroll
        for (int ks = 0; ks < 2; ks++) {
            const uint32_t kso = (uint32_t)(ks * 16) * 2;
            uint32_t ah[4][4];
#pragma unroll
            for (int mt = 0; mt < 4; mt++) {
                const uint32_t ro = (uint32_t)(mt * 16 * GSTR) * 2;
                ldsm_x4(ah[mt], uAh + a_off + ro + kso);
            }
#pragma unroll
            for (int pp = 0; pp < 2; pp++) {
                uint32_t bh[2][4];
#pragma unroll
                for (int q2 = 0; q2 < 2; q2++) {
                    const uint32_t ro =
                        (uint32_t)(((pp * 2 + q2) * 16) * GSTR) * 2;
                    ldsm_x4(bh[q2], uBh + b_off + ro + kso);
                }
#pragma unroll
                for (int q2 = 0; q2 < 2; q2++) {
                    const int nt = (pp * 2 + q2) * 2;
#pragma unroll
                    for (int mt = 0; mt < 4; mt++) {
                        mma16816h(acc[mt][nt],     ah[mt], bh[q2][0], bh[q2][1]);
                        mma16816h(acc[mt][nt + 1], ah[mt], bh[q2][2], bh[q2][3]);
                    }
                }
            }
        }

        __syncthreads();
        if (s + 2 < nsteps) issue(s + 2);
    }

    // ---- epilogue --------------------------------------------------------
#pragma unroll
    for (int mt = 0; mt < 4; mt++) {
#pragma unroll
        for (int nt = 0; nt < 8; nt++) {
            const int m = m0 + wm * 64 + mt * 16 + g;
            const int n = n0 + wn * 64 + nt * 8 + t * 2;
            const float* c = acc[mt][nt];
            float2 bv = *(const float2*)(bias + n);
            if (MODE == 0) {
                *(float2*)(C + (size_t)m * N + n) =
                    make_float2(c[0] + bv.x, c[1] + bv.y);
                *(float2*)(C + (size_t)(m + 8) * N + n) =
                    make_float2(c[2] + bv.x, c[3] + bv.y);
            } else {
                const int which = n >> 10;
                const int h = (n >> 6) & 15;
                const int d = n & 63;
#pragma unroll
                for (int rr = 0; rr < 2; rr++) {
                    const int mm = m + rr * 8;
                    const int b = mm >> 11, s = mm & 2047;
                    float v0 = c[rr * 2 + 0] + bv.x;
                    float v1 = c[rr * 2 + 1] + bv.y;
                    if (which == 2) {
                        // V: write transposed [bh][d][s]
                        __half* vt = g_vth +
                            (((size_t)b * H_ + h) * D_) * S_ + s;
                        vt[(size_t)d * S_]       = __float2half_rn(v0);
                        vt[(size_t)(d + 1) * S_] = __float2half_rn(v1);
                    } else {
                        const float sc = (which == 1) ? QSCALE : 1.0f;
                        __half* dst = (which == 0) ? g_kh : g_qh;
                        const size_t off =
                            ((((size_t)b * H_ + h) * S_) + s) * D_ + d;
                        *(uint32_t*)(dst + off) =
                            pack_f16x2(v0 * sc, v1 * sc);
                    }
                }
            }
        }
    }
}

// ---------------------------------------------------------------------------
// Tensor-core causal flash attention, pure fp16 (R12/13 config).
// CTA = (q-tile 128, bh), 8 warps, 2-stage KV ring, 2 CTAs/SM.
// ---------------------------------------------------------------------------
constexpr int ASTR = 72;
constexpr int AQ_E = 128 * ASTR;
constexpr int AKT_E = 64 * ASTR;
constexpr int AKSTAGE_E = 2 * AKT_E;            // kh, vth
constexpr int ASMEM = (AQ_E + 2 * AKSTAGE_E) * 2;   // 55296 B

__global__ __launch_bounds__(256, 2) void attn_mma() {
    extern __shared__ __half sma[];
    const uint32_t sma_u = smem_u32(sma);
    const int tid = threadIdx.x;
    const int lane = tid & 31;
    const int w = tid >> 5;
    const int g = lane >> 2, t = lane & 3;
    const int qt = (S_ / 128 - 1) - blockIdx.x;
    const int bh = blockIdx.y;
    const int nkt = 2 * qt + 2;

    __half* QH = sma;
    const uint32_t KV0_u = sma_u + AQ_E * 2;

    {
        const __half* qsrc = g_qh + ((size_t)bh * S_ + qt * 128) * D_;
#pragma unroll
        for (int c = 0; c < 4; c++) {
            int ci = tid + c * 256;
            int r = ci >> 3, ch = ci & 7;
            cp16(smem_u32(sma + r * ASTR + ch * 8),
                 qsrc + (size_t)r * D_ + ch * 8);
        }
        CP_COMMIT();
    }

    auto issueKV = [&](int kt) {
        uint32_t st = KV0_u + (uint32_t)((kt & 1) * AKSTAGE_E) * 2;
        const __half* bases[2] = {
            g_kh + ((size_t)bh * S_ + kt * 64) * D_,
            g_vth + (size_t)bh * D_ * S_ + kt * 64 };
#pragma unroll
        for (int c = 0; c < 4; c++) {
            int ci = tid + c * 256;
            int arr = ci >> 9;
            int idx = ci & 511;
            int r = idx >> 3, ch = idx & 7;
            const size_t rs = (arr == 0) ? (size_t)D_ : (size_t)S_;
            cp16(st + (uint32_t)(arr * AKT_E + r * ASTR + ch * 8) * 2,
                 bases[arr] + (size_t)r * rs + ch * 8);
        }
        CP_COMMIT();
    };

    issueKV(0);
    CP_WAIT1();
    __syncthreads();

    uint32_t qfh[4][4];
#pragma unroll
    for (int ks = 0; ks < 4; ks++) {
        const int kb = ks * 16 + t * 2;
        const int r0 = (w * 16 + g) * ASTR;
        qfh[ks][0] = *(const uint32_t*)(QH + r0 + kb);
        qfh[ks][1] = *(const uint32_t*)(QH + r0 + 8 * ASTR + kb);
        qfh[ks][2] = *(const uint32_t*)(QH + r0 + kb + 8);
        qfh[ks][3] = *(const uint32_t*)(QH + r0 + 8 * ASTR + kb + 8);
    }

    const uint32_t bfrag_off =
        (uint32_t)((((lane >> 4) & 1) * 8 + (lane & 7)) * ASTR +
                   ((lane >> 3) & 1) * 8) * 2;

    float o[8][4];
#pragma unroll
    for (int nt = 0; nt < 8; nt++)
#pragma unroll
        for (int e = 0; e < 4; e++) o[nt][e] = 0.f;
    float m0 = -1e30f, m1 = -1e30f, l0 = 0.f, l1 = 0.f;

    const int row0 = qt * 128 + w * 16 + g;
    const int row1 = row0 + 8;

    for (int kt = 0; kt < nkt; kt++) {
        CP_WAIT0();
        __syncthreads();
        if (kt + 1 < nkt) issueKV(kt + 1);

        if (kt * 64 > qt * 128 + w * 16 + 15) continue;

        const uint32_t st = KV0_u + (uint32_t)((kt & 1) * AKSTAGE_E) * 2;
        const uint32_t uKH = st;
        const uint32_t uVH = st + AKT_E * 2;

        float sc[8][4];
#pragma unroll
        for (int nt = 0; nt < 8; nt++)
#pragma unroll
            for (int e = 0; e < 4; e++) sc[nt][e] = 0.f;

#pragma unroll
        for (int ks = 0; ks < 4; ks++) {
            const uint32_t kso = (uint32_t)(ks * 16) * 2;
            uint32_t kh4[4][4];
#pragma unroll
            for (int ntp = 0; ntp < 4; ntp++) {
                const uint32_t ro = (uint32_t)((ntp * 16) * ASTR) * 2;
                ldsm_x4(kh4[ntp], uKH + bfrag_off + ro + kso);
            }
#pragma unroll
            for (int ntp = 0; ntp < 4; ntp++) {
                mma16816h(sc[2 * ntp],     qfh[ks], kh4[ntp][0], kh4[ntp][1]);
                mma16816h(sc[2 * ntp + 1], qfh[ks], kh4[ntp][2], kh4[ntp][3]);
            }
        }

        if (kt >= 2 * qt) {
#pragma unroll
            for (int nt = 0; nt < 8; nt++) {
                const int c0 = kt * 64 + nt * 8 + 2 * t;
                if (c0 > row0)     sc[nt][0] = -1e30f;
                if (c0 + 1 > row0) sc[nt][1] = -1e30f;
                if (c0 > row1)     sc[nt][2] = -1e30f;
                if (c0 + 1 > row1) sc[nt][3] = -1e30f;
            }
        }

        float mx0 = -1e30f, mx1 = -1e30f;
#pragma unroll
        for (int nt = 0; nt < 8; nt++) {
            mx0 = fmaxf(mx0, fmaxf(sc[nt][0], sc[nt][1]));
            mx1 = fmaxf(mx1, fmaxf(sc[nt][2], sc[nt][3]));
        }
        mx0 = fmaxf(mx0, __shfl_xor_sync(0xffffffffu, mx0, 1));
        mx0 = fmaxf(mx0, __shfl_xor_sync(0xffffffffu, mx0, 2));
        mx1 = fmaxf(mx1, __shfl_xor_sync(0xffffffffu, mx1, 1));
        mx1 = fmaxf(mx1, __shfl_xor_sync(0xffffffffu, mx1, 2));

        const float mn0 = fmaxf(m0, mx0), mn1 = fmaxf(m1, mx1);
        const float a0 = exp2p(m0 - mn0), a1 = exp2p(m1 - mn1);
        m0 = mn0; m1 = mn1;

        float rs0 = 0.f, rs1 = 0.f;
#pragma unroll
        for (int nt = 0; nt < 8; nt++) {
            sc[nt][0] = exp2p(sc[nt][0] - mn0);
            sc[nt][1] = exp2p(sc[nt][1] - mn0);
            sc[nt][2] = exp2p(sc[nt][2] - mn1);
            sc[nt][3] = exp2p(sc[nt][3] - mn1);
            rs0 += sc[nt][0] + sc[nt][1];
            rs1 += sc[nt][2] + sc[nt][3];
        }
        rs0 += __shfl_xor_sync(0xffffffffu, rs0, 1);
        rs0 += __shfl_xor_sync(0xffffffffu, rs0, 2);
        rs1 += __shfl_xor_sync(0xffffffffu, rs1, 1);
        rs1 += __shfl_xor_sync(0xffffffffu, rs1, 2);
        l0 = l0 * a0 + rs0;
        l1 = l1 * a1 + rs1;

#pragma unroll
        for (int nt = 0; nt < 8; nt++) {
            o[nt][0] *= a0; o[nt][1] *= a0;
            o[nt][2] *= a1; o[nt][3] *= a1;
        }

        uint32_t pfh[4][4];
#pragma unroll
        for (int ks = 0; ks < 4; ks++) {
            const float* p0 = sc[2 * ks];
            const float* p1 = sc[2 * ks + 1];
            pfh[ks][0] = pack_f16x2(p0[0], p0[1]);
            pfh[ks][1] = pack_f16x2(p0[2], p0[3]);
            pfh[ks][2] = pack_f16x2(p1[0], p1[1]);
            pfh[ks][3] = pack_f16x2(p1[2], p1[3]);
        }

#pragma unroll
        for (int ks = 0; ks < 4; ks++) {
            const uint32_t kso = (uint32_t)(ks * 16) * 2;
            uint32_t vh4[4][4];
#pragma unroll
            for (int ntp = 0; ntp < 4; ntp++) {
                const uint32_t ro = (uint32_t)((ntp * 16) * ASTR) * 2;
                ldsm_x4(vh4[ntp], uVH + bfrag_off + ro + kso);
            }
#pragma unroll
            for (int ntp = 0; ntp < 4; ntp++) {
                mma16816h(o[2 * ntp],     pfh[ks], vh4[ntp][0], vh4[ntp][1]);
                mma16816h(o[2 * ntp + 1], pfh[ks], vh4[ntp][2], vh4[ntp][3]);
            }
        }
    }

    const float inv0 = 1.0f / l0, inv1 = 1.0f / l1;
    const int b = bh >> 4, h = bh & 15;
#pragma unroll
    for (int nt = 0; nt < 8; nt++) {
        const int e = h * 64 + nt * 8 + 2 * t;
        {
            const size_t off = ((size_t)b * S_ + row0) * E_ + e;
            *(uint32_t*)(g_yh + off) =
                pack_f16x2(o[nt][0] * inv0, o[nt][1] * inv0);
        }
        {
            const size_t off = ((size_t)b * S_ + row1) * E_ + e;
            *(uint32_t*)(g_yh + off) =
                pack_f16x2(o[nt][2] * inv1, o[nt][3] * inv1);
        }
    }
}

// ---------------------------------------------------------------------------
// Launch
// ---------------------------------------------------------------------------
extern "C" void kernel_launch(void* const* d_in, const int* in_sizes, int n_in,
                              void* d_out, int out_size)
{
    const float* x      = (const float*)d_in[0];
    const float* W_kqv  = (const float*)d_in[1];
    const float* b_kqv  = (const float*)d_in[2];
    const float* W_proj = (const float*)d_in[3];
    const float* b_proj = (const float*)d_in[4];
    float* out = (float*)d_out;

    void *xh, *wkh, *wph, *yh;
    cudaGetSymbolAddress(&xh, g_xh);
    cudaGetSymbolAddress(&wkh, g_wkh);
    cudaGetSymbolAddress(&wph, g_wph);
    cudaGetSymbolAddress(&yh, g_yh);

    cudaFuncSetAttribute(gemm_h1<0>, cudaFuncAttributeMaxDynamicSharedMemorySize, PSMEM);
    cudaFuncSetAttribute(gemm_h1<1>, cudaFuncAttributeMaxDynamicSharedMemorySize, PSMEM);
    cudaFuncSetAttribute(attn_mma,  cudaFuncAttributeMaxDynamicSharedMemorySize, ASMEM);

    // 0) conversions
    {
        int n4 = M_ * E_ / 4;
        convH_kernel<<<(n4 + 255) / 256, 256>>>(x, (__half*)xh, n4);
        n4 = NKQV * E_ / 4;
        convH_kernel<<<(n4 + 255) / 256, 256>>>(W_kqv, (__half*)wkh, n4);
        n4 = E_ * E_ / 4;
        convH_kernel<<<(n4 + 255) / 256, 256>>>(W_proj, (__half*)wph, n4);
    }

    // 1) QKV projection -> q/k (natural), v (transposed)
    gemm_h1<1><<<dim3(NKQV / 128, M_ / 128), 128, PSMEM>>>(
        (const __half*)xh, (const __half*)wkh, b_kqv, nullptr, NKQV, E_);

    // 2) Tensor-core causal flash attention -> y fp16
    attn_mma<<<dim3(S_ / 128, B_ * H_), 256, ASMEM>>>();

    // 3) Output projection -> d_out
    gemm_h1<0><<<dim3(E_ / 128, M_ / 128), 128, PSMEM>>>(
        (const __half*)yh, (const __half*)wph, b_proj, out, E_, E_);
}

// round 16
// speedup vs baseline: 1.0481x; 1.0481x over previous
#include <cuda_runtime.h>
#include <cuda_fp16.h>
#include <cstdint>
#include <math.h>

// Problem constants
constexpr int B_ = 4, S_ = 2048, E_ = 1024, H_ = 16, D_ = 64;
constexpr int M_ = B_ * S_;            // 8192 rows
constexpr int NKQV = 3 * E_;           // 3072

// ---------------------------------------------------------------------------
// Scratch (device globals; pure fp16)
// ---------------------------------------------------------------------------
__device__ __half g_xh[(size_t)M_ * E_];
__device__ __half g_wkh[(size_t)NKQV * E_];
__device__ __half g_wph[(size_t)E_ * E_];
__device__ __half g_qh[(size_t)B_*H_*S_*D_];
__device__ __half g_kh[(size_t)B_*H_*S_*D_];
__device__ __half g_vh[(size_t)B_*H_*S_*D_];
__device__ __half g_vth[(size_t)B_*H_*S_*D_];
__device__ __half g_yh[(size_t)M_ * E_];

// ---------------------------------------------------------------------------
// helpers
// ---------------------------------------------------------------------------
__device__ __forceinline__ uint32_t pack_f16x2(float a, float b) {
    __half2 h = __floats2half2_rn(a, b);
    return *(uint32_t*)&h;
}

__device__ __forceinline__ void mma16816h(float* c, const uint32_t* a,
                                          uint32_t b0, uint32_t b1) {
    asm volatile(
        "mma.sync.aligned.m16n8k16.row.col.f32.f16.f16.f32 "
        "{%0,%1,%2,%3}, {%4,%5,%6,%7}, {%8,%9}, {%0,%1,%2,%3};"
        : "+f"(c[0]), "+f"(c[1]), "+f"(c[2]), "+f"(c[3])
        : "r"(a[0]), "r"(a[1]), "r"(a[2]), "r"(a[3]), "r"(b0), "r"(b1));
}

__device__ __forceinline__ void ldsm_x4(uint32_t* r, uint32_t addr) {
    asm volatile(
        "ldmatrix.sync.aligned.m8n8.x4.shared.b16 {%0,%1,%2,%3}, [%4];"
        : "=r"(r[0]), "=r"(r[1]), "=r"(r[2]), "=r"(r[3]) : "r"(addr));
}

__device__ __forceinline__ uint32_t smem_u32(const void* p) {
    uint32_t a;
    asm("{ .reg .u64 t; cvta.to.shared.u64 t, %1; cvt.u32.u64 %0, t; }"
        : "=r"(a) : "l"(p));
    return a;
}
__device__ __forceinline__ void cp16(uint32_t dst, const void* src) {
    asm volatile("cp.async.ca.shared.global [%0], [%1], 16;"
                 :: "r"(dst), "l"(src));
}
#define CP_COMMIT() asm volatile("cp.async.commit_group;" ::: "memory")
#define CP_WAIT1()  asm volatile("cp.async.wait_group 1;" ::: "memory")
#define CP_WAIT0()  asm volatile("cp.async.wait_group 0;" ::: "memory")

// FMA-pipe exp2, degree-3 minimax (Chebyshev-economized). ~7.5e-5 rel err,
// below the fp16 rounding applied to P. 3 FMA + clamp + range reduction.
__device__ __forceinline__ float exp2p(float x) {
    x = fmaxf(x, -80.f);
    float t = x + 12582912.f;               // round-to-nearest-int magic
    int n = __float_as_int(t) - 0x4B400000;
    float r = x - (t - 12582912.f);         // r in [-0.5, 0.5]
    float p = 5.55041087e-2f;
    p = fmaf(p, r, 2.42630219e-1f);
    p = fmaf(p, r, 6.93147180e-1f);
    p = fmaf(p, r, 9.99924860e-1f);
    return p * __int_as_float((n + 127) << 23);
}

constexpr float QSCALE = 0.125f * 1.44269504088896340736f;

// ---------------------------------------------------------------------------
// conversion: fp32 -> fp16, all three arrays in ONE launch (segment dispatch)
// ---------------------------------------------------------------------------
constexpr int CN_X = M_ * E_ / 4;            // 2097152
constexpr int CN_WK = NKQV * E_ / 4;         // 786432
constexpr int CN_WP = E_ * E_ / 4;           // 262144
constexpr int CN_TOT = CN_X + CN_WK + CN_WP;

__global__ void convAll_kernel(const float* __restrict__ x,
                               const float* __restrict__ wk,
                               const float* __restrict__ wp) {
    int i = blockIdx.x * blockDim.x + threadIdx.x;
    if (i >= CN_TOT) return;
    const float* src;
    __half* dst;
    int j;
    if (i < CN_X) {
        src = x; dst = g_xh; j = i;
    } else if (i < CN_X + CN_WK) {
        src = wk; dst = g_wkh; j = i - CN_X;
    } else {
        src = wp; dst = g_wph; j = i - CN_X - CN_WK;
    }
    float4 v = ((const float4*)src)[j];
    ((uint2*)dst)[j] = make_uint2(pack_f16x2(v.x, v.y), pack_f16x2(v.z, v.w));
}

// ---------------------------------------------------------------------------
// GEMM (pure fp16, single MMA; EXACT R13 config): C = Ah @ Bh^T + bias.
// 128x128x32 tiles, 4 warps of 64x64, 128 threads, 2-stage, 2 CTAs/SM.
// MODE 0: fp32 out. MODE 1: scatter q/k/v (natural layout).
// ---------------------------------------------------------------------------
constexpr int GBK = 32;
constexpr int GSTR = 40;
constexpr int GTILE_E = 128 * GSTR;          // 5120
constexpr int PSTAGE_E = 2 * GTILE_E;        // Ah, Bh
constexpr int PSMEM = 2 * PSTAGE_E * 2;      // 40960 B -> 2 CTAs/SM

template <int MODE>
__global__ __launch_bounds__(128, 2) void gemm_h1(
    const __half* __restrict__ Ah, const __half* __restrict__ Bh,
    const float* __restrict__ bias, float* __restrict__ C, int N, int K)
{
    extern __shared__ __half smh[];
    const uint32_t smb_u = smem_u32(smh);
    const int tid = threadIdx.x;
    const int lane = tid & 31;
    const int w = tid >> 5;
    const int wm = w & 1, wn = w >> 1;
    const int g = lane >> 2, t = lane & 3;
    const int m0 = blockIdx.y * 128;
    const int n0 = blockIdx.x * 128;

    const __half* bases[2] = { Ah + (size_t)m0 * K, Bh + (size_t)n0 * K };

    const int nsteps = K / GBK;

    auto issue = [&](int s) {
        __half* st = smh + (s & 1) * PSTAGE_E;
        const int k0 = s * GBK;
#pragma unroll
        for (int c = 0; c < 8; c++) {
            int ci = tid + c * 128;
            int arr = ci >> 9;
            int idx = ci & 511;
            int r = idx >> 2, ch = idx & 3;
            cp16(smem_u32(st + arr * GTILE_E + r * GSTR + ch * 8),
                 bases[arr] + (size_t)r * K + k0 + ch * 8);
        }
        CP_COMMIT();
    };

    const uint32_t a_off =
        (uint32_t)((wm * 64 + (lane & 15)) * GSTR + (lane >> 4) * 8) * 2;
    const uint32_t b_off =
        (uint32_t)((wn * 64 + ((lane >> 4) & 1) * 8 + (lane & 7)) * GSTR +
                   ((lane >> 3) & 1) * 8) * 2;

    float acc[4][8][4];
#pragma unroll
    for (int i = 0; i < 4; i++)
#pragma unroll
        for (int j = 0; j < 8; j++)
#pragma unroll
            for (int e = 0; e < 4; e++) acc[i][j][e] = 0.f;

    issue(0);
    issue(1);

    for (int s = 0; s < nsteps; s++) {
        if (s + 1 < nsteps) { CP_WAIT1(); } else { CP_WAIT0(); }
        __syncthreads();

        const uint32_t st = smb_u + (uint32_t)((s & 1) * PSTAGE_E) * 2;
        const uint32_t uAh = st;
        const uint32_t uBh = st + GTILE_E * 2;

#pragma unroll
        for (int ks = 0; ks < 2; ks++) {
            const uint32_t kso = (uint32_t)(ks * 16) * 2;
            uint32_t ah[4][4];
#pragma unroll
            for (int mt = 0; mt < 4; mt++) {
                const uint32_t ro = (uint32_t)(mt * 16 * GSTR) * 2;
                ldsm_x4(ah[mt], uAh + a_off + ro + kso);
            }
#pragma unroll
            for (int pp = 0; pp < 2; pp++) {
                uint32_t bh[2][4];
#pragma unroll
                for (int q2 = 0; q2 < 2; q2++) {
                    const uint32_t ro =
                        (uint32_t)(((pp * 2 + q2) * 16) * GSTR) * 2;
                    ldsm_x4(bh[q2], uBh + b_off + ro + kso);
                }
#pragma unroll
                for (int q2 = 0; q2 < 2; q2++) {
                    const int nt = (pp * 2 + q2) * 2;
#pragma unroll
                    for (int mt = 0; mt < 4; mt++) {
                        mma16816h(acc[mt][nt],     ah[mt], bh[q2][0], bh[q2][1]);
                        mma16816h(acc[mt][nt + 1], ah[mt], bh[q2][2], bh[q2][3]);
                    }
                }
            }
        }

        __syncthreads();
        if (s + 2 < nsteps) issue(s + 2);
    }

    // ---- epilogue --------------------------------------------------------
#pragma unroll
    for (int mt = 0; mt < 4; mt++) {
#pragma unroll
        for (int nt = 0; nt < 8; nt++) {
            const int m = m0 + wm * 64 + mt * 16 + g;
            const int n = n0 + wn * 64 + nt * 8 + t * 2;
            const float* c = acc[mt][nt];
            float2 bv = *(const float2*)(bias + n);
            if (MODE == 0) {
                *(float2*)(C + (size_t)m * N + n) =
                    make_float2(c[0] + bv.x, c[1] + bv.y);
                *(float2*)(C + (size_t)(m + 8) * N + n) =
                    make_float2(c[2] + bv.x, c[3] + bv.y);
            } else {
                const int which = n >> 10;
                const int h = (n >> 6) & 15;
                const int d = n & 63;
                const float sc = (which == 1) ? QSCALE : 1.0f;
                __half* dst = (which == 0) ? g_kh : (which == 1) ? g_qh : g_vh;
#pragma unroll
                for (int rr = 0; rr < 2; rr++) {
                    const int mm = m + rr * 8;
                    const int b = mm >> 11, s = mm & 2047;
                    const size_t off =
                        ((((size_t)b * H_ + h) * S_) + s) * D_ + d;
                    *(uint32_t*)(dst + off) =
                        pack_f16x2((c[rr * 2 + 0] + bv.x) * sc,
                                   (c[rr * 2 + 1] + bv.y) * sc);
                }
            }
        }
    }
}

// ---------------------------------------------------------------------------
// V transpose: [bh][s][d] -> [bh][d][s] (fp16)
// ---------------------------------------------------------------------------
__global__ __launch_bounds__(256) void vtrans_kernel() {
    __shared__ __half tile[64][72];
    const int tid = threadIdx.x;
    const int st = blockIdx.x;
    const int bh = blockIdx.y;

    const __half* src = g_vh + ((size_t)bh * S_ + st * 64) * D_;
    __half* dst = g_vth + (size_t)bh * D_ * S_ + st * 64;

#pragma unroll
    for (int c = 0; c < 8; c++) {
        int ci = tid + c * 256;
        int r = ci >> 5, ch = ci & 31;
        *(uint32_t*)&tile[r][ch * 2] =
            *(const uint32_t*)(src + (size_t)r * D_ + ch * 2);
    }
    __syncthreads();
#pragma unroll
    for (int c = 0; c < 8; c++) {
        int ci = tid + c * 256;
        int d = ci >> 5, s2 = (ci & 31) * 2;
        __half2 o = __halves2half2(tile[s2][d], tile[s2 + 1][d]);
        *(uint32_t*)(dst + (size_t)d * S_ + s2) = *(uint32_t*)&o;
    }
}

// ---------------------------------------------------------------------------
// Tensor-core causal flash attention, pure fp16 (R13 config, deg-3 exp2).
// CTA = (q-tile 128, bh), 8 warps, 2-stage KV ring, 2 CTAs/SM.
// ---------------------------------------------------------------------------
constexpr int ASTR = 72;
constexpr int AQ_E = 128 * ASTR;
constexpr int AKT_E = 64 * ASTR;
constexpr int AKSTAGE_E = 2 * AKT_E;            // kh, vth
constexpr int ASMEM = (AQ_E + 2 * AKSTAGE_E) * 2;   // 55296 B

__global__ __launch_bounds__(256, 2) void attn_mma() {
    extern __shared__ __half sma[];
    const uint32_t sma_u = smem_u32(sma);
    const int tid = threadIdx.x;
    const int lane = tid & 31;
    const int w = tid >> 5;
    const int g = lane >> 2, t = lane & 3;
    const int qt = (S_ / 128 - 1) - blockIdx.x;
    const int bh = blockIdx.y;
    const int nkt = 2 * qt + 2;

    __half* QH = sma;
    const uint32_t KV0_u = sma_u + AQ_E * 2;

    {
        const __half* qsrc = g_qh + ((size_t)bh * S_ + qt * 128) * D_;
#pragma unroll
        for (int c = 0; c < 4; c++) {
            int ci = tid + c * 256;
            int r = ci >> 3, ch = ci & 7;
            cp16(smem_u32(sma + r * ASTR + ch * 8),
                 qsrc + (size_t)r * D_ + ch * 8);
        }
        CP_COMMIT();
    }

    auto issueKV = [&](int kt) {
        uint32_t st = KV0_u + (uint32_t)((kt & 1) * AKSTAGE_E) * 2;
        const __half* bases[2] = {
            g_kh + ((size_t)bh * S_ + kt * 64) * D_,
            g_vth + (size_t)bh * D_ * S_ + kt * 64 };
#pragma unroll
        for (int c = 0; c < 4; c++) {
            int ci = tid + c * 256;
            int arr = ci >> 9;
            int idx = ci & 511;
            int r = idx >> 3, ch = idx & 7;
            const size_t rs = (arr == 0) ? (size_t)D_ : (size_t)S_;
            cp16(st + (uint32_t)(arr * AKT_E + r * ASTR + ch * 8) * 2,
                 bases[arr] + (size_t)r * rs + ch * 8);
        }
        CP_COMMIT();
    };

    issueKV(0);
    CP_WAIT1();
    __syncthreads();

    uint32_t qfh[4][4];
#pragma unroll
    for (int ks = 0; ks < 4; ks++) {
        const int kb = ks * 16 + t * 2;
        const int r0 = (w * 16 + g) * ASTR;
        qfh[ks][0] = *(const uint32_t*)(QH + r0 + kb);
        qfh[ks][1] = *(const uint32_t*)(QH + r0 + 8 * ASTR + kb);
        qfh[ks][2] = *(const uint32_t*)(QH + r0 + kb + 8);
        qfh[ks][3] = *(const uint32_t*)(QH + r0 + 8 * ASTR + kb + 8);
    }

    const uint32_t bfrag_off =
        (uint32_t)((((lane >> 4) & 1) * 8 + (lane & 7)) * ASTR +
                   ((lane >> 3) & 1) * 8) * 2;

    float o[8][4];
#pragma unroll
    for (int nt = 0; nt < 8; nt++)
#pragma unroll
        for (int e = 0; e < 4; e++) o[nt][e] = 0.f;
    float m0 = -1e30f, m1 = -1e30f, l0 = 0.f, l1 = 0.f;

    const int row0 = qt * 128 + w * 16 + g;
    const int row1 = row0 + 8;

    for (int kt = 0; kt < nkt; kt++) {
        CP_WAIT0();
        __syncthreads();
        if (kt + 1 < nkt) issueKV(kt + 1);

        if (kt * 64 > qt * 128 + w * 16 + 15) continue;

        const uint32_t st = KV0_u + (uint32_t)((kt & 1) * AKSTAGE_E) * 2;
        const uint32_t uKH = st;
        const uint32_t uVH = st + AKT_E * 2;

        float sc[8][4];
#pragma unroll
        for (int nt = 0; nt < 8; nt++)
#pragma unroll
            for (int e = 0; e < 4; e++) sc[nt][e] = 0.f;

#pragma unroll
        for (int ks = 0; ks < 4; ks++) {
            const uint32_t kso = (uint32_t)(ks * 16) * 2;
            uint32_t kh4[4][4];
#pragma unroll
            for (int ntp = 0; ntp < 4; ntp++) {
                const uint32_t ro = (uint32_t)((ntp * 16) * ASTR) * 2;
                ldsm_x4(kh4[ntp], uKH + bfrag_off + ro + kso);
            }
#pragma unroll
            for (int ntp = 0; ntp < 4; ntp++) {
                mma16816h(sc[2 * ntp],     qfh[ks], kh4[ntp][0], kh4[ntp][1]);
                mma16816h(sc[2 * ntp + 1], qfh[ks], kh4[ntp][2], kh4[ntp][3]);
            }
        }

        if (kt >= 2 * qt) {
#pragma unroll
            for (int nt = 0; nt < 8; nt++) {
                const int c0 = kt * 64 + nt * 8 + 2 * t;
                if (c0 > row0)     sc[nt][0] = -1e30f;
                if (c0 + 1 > row0) sc[nt][1] = -1e30f;
                if (c0 > row1)     sc[nt][2] = -1e30f;
                if (c0 + 1 > row1) sc[nt][3] = -1e30f;
            }
        }

        float mx0 = -1e30f, mx1 = -1e30f;
#pragma unroll
        for (int nt = 0; nt < 8; nt++) {
            mx0 = fmaxf(mx0, fmaxf(sc[nt][0], sc[nt][1]));
            mx1 = fmaxf(mx1, fmaxf(sc[nt][2], sc[nt][3]));
        }
        mx0 = fmaxf(mx0, __shfl_xor_sync(0xffffffffu, mx0, 1));
        mx0 = fmaxf(mx0, __shfl_xor_sync(0xffffffffu, mx0, 2));
        mx1 = fmaxf(mx1, __shfl_xor_sync(0xffffffffu, mx1, 1));
        mx1 = fmaxf(mx1, __shfl_xor_sync(0xffffffffu, mx1, 2));

        const float mn0 = fmaxf(m0, mx0), mn1 = fmaxf(m1, mx1);
        const float a0 = exp2p(m0 - mn0), a1 = exp2p(m1 - mn1);
        m0 = mn0; m1 = mn1;

        float rs0 = 0.f, rs1 = 0.f;
#pragma unroll
        for (int nt = 0; nt < 8; nt++) {
            sc[nt][0] = exp2p(sc[nt][0] - mn0);
            sc[nt][1] = exp2p(sc[nt][1] - mn0);
            sc[nt][2] = exp2p(sc[nt][2] - mn1);
            sc[nt][3] = exp2p(sc[nt][3] - mn1);
            rs0 += sc[nt][0] + sc[nt][1];
            rs1 += sc[nt][2] + sc[nt][3];
        }
        rs0 += __shfl_xor_sync(0xffffffffu, rs0, 1);
        rs0 += __shfl_xor_sync(0xffffffffu, rs0, 2);
        rs1 += __shfl_xor_sync(0xffffffffu, rs1, 1);
        rs1 += __shfl_xor_sync(0xffffffffu, rs1, 2);
        l0 = l0 * a0 + rs0;
        l1 = l1 * a1 + rs1;

#pragma unroll
        for (int nt = 0; nt < 8; nt++) {
            o[nt][0] *= a0; o[nt][1] *= a0;
            o[nt][2] *= a1; o[nt][3] *= a1;
        }

        uint32_t pfh[4][4];
#pragma unroll
        for (int ks = 0; ks < 4; ks++) {
            const float* p0 = sc[2 * ks];
            const float* p1 = sc[2 * ks + 1];
            pfh[ks][0] = pack_f16x2(p0[0], p0[1]);
            pfh[ks][1] = pack_f16x2(p0[2], p0[3]);
            pfh[ks][2] = pack_f16x2(p1[0], p1[1]);
            pfh[ks][3] = pack_f16x2(p1[2], p1[3]);
        }

#pragma unroll
        for (int ks = 0; ks < 4; ks++) {
            const uint32_t kso = (uint32_t)(ks * 16) * 2;
            uint32_t vh4[4][4];
#pragma unroll
            for (int ntp = 0; ntp < 4; ntp++) {
                const uint32_t ro = (uint32_t)((ntp * 16) * ASTR) * 2;
                ldsm_x4(vh4[ntp], uVH + bfrag_off + ro + kso);
            }
#pragma unroll
            for (int ntp = 0; ntp < 4; ntp++) {
                mma16816h(o[2 * ntp],     pfh[ks], vh4[ntp][0], vh4[ntp][1]);
                mma16816h(o[2 * ntp + 1], pfh[ks], vh4[ntp][2], vh4[ntp][3]);
            }
        }
    }

    const float inv0 = 1.0f / l0, inv1 = 1.0f / l1;
    const int b = bh >> 4, h = bh & 15;
#pragma unroll
    for (int nt = 0; nt < 8; nt++) {
        const int e = h * 64 + nt * 8 + 2 * t;
        {
            const size_t off = ((size_t)b * S_ + row0) * E_ + e;
            *(uint32_t*)(g_yh + off) =
                pack_f16x2(o[nt][0] * inv0, o[nt][1] * inv0);
        }
        {
            const size_t off = ((size_t)b * S_ + row1) * E_ + e;
            *(uint32_t*)(g_yh + off) =
                pack_f16x2(o[nt][2] * inv1, o[nt][3] * inv1);
        }
    }
}

// ---------------------------------------------------------------------------
// Launch
// ---------------------------------------------------------------------------
extern "C" void kernel_launch(void* const* d_in, const int* in_sizes, int n_in,
                              void* d_out, int out_size)
{
    const float* x      = (const float*)d_in[0];
    const float* W_kqv  = (const float*)d_in[1];
    const float* b_kqv  = (const float*)d_in[2];
    const float* W_proj = (const float*)d_in[3];
    const float* b_proj = (const float*)d_in[4];
    float* out = (float*)d_out;

    void *xh, *wkh, *wph, *yh;
    cudaGetSymbolAddress(&xh, g_xh);
    cudaGetSymbolAddress(&wkh, g_wkh);
    cudaGetSymbolAddress(&wph, g_wph);
    cudaGetSymbolAddress(&yh, g_yh);

    cudaFuncSetAttribute(gemm_h1<0>, cudaFuncAttributeMaxDynamicSharedMemorySize, PSMEM);
    cudaFuncSetAttribute(gemm_h1<1>, cudaFuncAttributeMaxDynamicSharedMemorySize, PSMEM);
    cudaFuncSetAttribute(attn_mma,  cudaFuncAttributeMaxDynamicSharedMemorySize, ASMEM);

    // 0) conversions (single launch)
    convAll_kernel<<<(CN_TOT + 255) / 256, 256>>>(x, W_kqv, W_proj);

    // 1) QKV projection -> q/k/v (fp16, natural)
    gemm_h1<1><<<dim3(NKQV / 128, M_ / 128), 128, PSMEM>>>(
        (const __half*)xh, (const __half*)wkh, b_kqv, nullptr, NKQV, E_);

    // 2) V transpose [bh][s][d] -> [bh][d][s]
    vtrans_kernel<<<dim3(S_ / 64, B_ * H_), 256>>>();

    // 3) Tensor-core causal flash attention -> y fp16
    attn_mma<<<dim3(S_ / 128, B_ * H_), 256, ASMEM>>>();

    // 4) Output projection -> d_out
    gemm_h1<0><<<dim3(E_ / 128, M_ / 128), 128, PSMEM>>>(
        (const __half*)yh, (const __half*)wph, b_proj, out, E_, E_);
}

// round 17
// speedup vs baseline: 1.1575x; 1.1044x over previous
#include <cuda_runtime.h>
#include <cuda_fp16.h>
#include <cstdint>
#include <math.h>

// Problem constants
constexpr int B_ = 4, S_ = 2048, E_ = 1024, H_ = 16, D_ = 64;
constexpr int M_ = B_ * S_;            // 8192 rows
constexpr int NKQV = 3 * E_;           // 3072

// ---------------------------------------------------------------------------
// Scratch (device globals; pure fp16)
// ---------------------------------------------------------------------------
__device__ __half g_xh[(size_t)M_ * E_];
__device__ __half g_wkh[(size_t)NKQV * E_];
__device__ __half g_wph[(size_t)E_ * E_];
__device__ __half g_qh[(size_t)B_*H_*S_*D_];
__device__ __half g_kh[(size_t)B_*H_*S_*D_];
__device__ __half g_vh[(size_t)B_*H_*S_*D_];
__device__ __half g_vth[(size_t)B_*H_*S_*D_];
__device__ __half g_yh[(size_t)M_ * E_];

// ---------------------------------------------------------------------------
// helpers
// ---------------------------------------------------------------------------
__device__ __forceinline__ uint32_t pack_f16x2(float a, float b) {
    __half2 h = __floats2half2_rn(a, b);
    return *(uint32_t*)&h;
}

__device__ __forceinline__ uint32_t h2exp2(uint32_t x) {
    uint32_t r;
    asm volatile("ex2.approx.f16x2 %0, %1;" : "=r"(r) : "r"(x));
    return r;
}

__device__ __forceinline__ void mma16816h(float* c, const uint32_t* a,
                                          uint32_t b0, uint32_t b1) {
    asm volatile(
        "mma.sync.aligned.m16n8k16.row.col.f32.f16.f16.f32 "
        "{%0,%1,%2,%3}, {%4,%5,%6,%7}, {%8,%9}, {%0,%1,%2,%3};"
        : "+f"(c[0]), "+f"(c[1]), "+f"(c[2]), "+f"(c[3])
        : "r"(a[0]), "r"(a[1]), "r"(a[2]), "r"(a[3]), "r"(b0), "r"(b1));
}

__device__ __forceinline__ void ldsm_x4(uint32_t* r, uint32_t addr) {
    asm volatile(
        "ldmatrix.sync.aligned.m8n8.x4.shared.b16 {%0,%1,%2,%3}, [%4];"
        : "=r"(r[0]), "=r"(r[1]), "=r"(r[2]), "=r"(r[3]) : "r"(addr));
}

__device__ __forceinline__ uint32_t smem_u32(const void* p) {
    uint32_t a;
    asm("{ .reg .u64 t; cvta.to.shared.u64 t, %1; cvt.u32.u64 %0, t; }"
        : "=r"(a) : "l"(p));
    return a;
}
__device__ __forceinline__ void cp16(uint32_t dst, const void* src) {
    asm volatile("cp.async.ca.shared.global [%0], [%1], 16;"
                 :: "r"(dst), "l"(src));
}
#define CP_COMMIT() asm volatile("cp.async.commit_group;" ::: "memory")
#define CP_WAIT1()  asm volatile("cp.async.wait_group 1;" ::: "memory")
#define CP_WAIT0()  asm volatile("cp.async.wait_group 0;" ::: "memory")

// FMA-pipe exp2, degree-3 minimax (for the alpha rescale factors only).
__device__ __forceinline__ float exp2p(float x) {
    x = fmaxf(x, -80.f);
    float t = x + 12582912.f;
    int n = __float_as_int(t) - 0x4B400000;
    float r = x - (t - 12582912.f);
    float p = 5.55041087e-2f;
    p = fmaf(p, r, 2.42630219e-1f);
    p = fmaf(p, r, 6.93147180e-1f);
    p = fmaf(p, r, 9.99924860e-1f);
    return p * __int_as_float((n + 127) << 23);
}

constexpr float QSCALE = 0.125f * 1.44269504088896340736f;

// ---------------------------------------------------------------------------
// conversion: fp32 -> fp16, all three arrays in ONE launch
// ---------------------------------------------------------------------------
constexpr int CN_X = M_ * E_ / 4;
constexpr int CN_WK = NKQV * E_ / 4;
constexpr int CN_WP = E_ * E_ / 4;
constexpr int CN_TOT = CN_X + CN_WK + CN_WP;

__global__ void convAll_kernel(const float* __restrict__ x,
                               const float* __restrict__ wk,
                               const float* __restrict__ wp) {
    int i = blockIdx.x * blockDim.x + threadIdx.x;
    if (i >= CN_TOT) return;
    const float* src;
    __half* dst;
    int j;
    if (i < CN_X) {
        src = x; dst = g_xh; j = i;
    } else if (i < CN_X + CN_WK) {
        src = wk; dst = g_wkh; j = i - CN_X;
    } else {
        src = wp; dst = g_wph; j = i - CN_X - CN_WK;
    }
    float4 v = ((const float4*)src)[j];
    ((uint2*)dst)[j] = make_uint2(pack_f16x2(v.x, v.y), pack_f16x2(v.z, v.w));
}

// ---------------------------------------------------------------------------
// GEMM (pure fp16, single MMA; R13 config): C = Ah @ Bh^T + bias.
// 128x128x32 tiles, 4 warps of 64x64, 128 threads, 2-stage, 2 CTAs/SM.
// ---------------------------------------------------------------------------
constexpr int GBK = 32;
constexpr int GSTR = 40;
constexpr int GTILE_E = 128 * GSTR;          // 5120
constexpr int PSTAGE_E = 2 * GTILE_E;
constexpr int PSMEM = 2 * PSTAGE_E * 2;      // 40960 B

template <int MODE>
__global__ __launch_bounds__(128, 2) void gemm_h1(
    const __half* __restrict__ Ah, const __half* __restrict__ Bh,
    const float* __restrict__ bias, float* __restrict__ C, int N, int K)
{
    extern __shared__ __half smh[];
    const uint32_t smb_u = smem_u32(smh);
    const int tid = threadIdx.x;
    const int lane = tid & 31;
    const int w = tid >> 5;
    const int wm = w & 1, wn = w >> 1;
    const int g = lane >> 2, t = lane & 3;
    const int m0 = blockIdx.y * 128;
    const int n0 = blockIdx.x * 128;

    const __half* bases[2] = { Ah + (size_t)m0 * K, Bh + (size_t)n0 * K };

    const int nsteps = K / GBK;

    auto issue = [&](int s) {
        __half* st = smh + (s & 1) * PSTAGE_E;
        const int k0 = s * GBK;
#pragma unroll
        for (int c = 0; c < 8; c++) {
            int ci = tid + c * 128;
            int arr = ci >> 9;
            int idx = ci & 511;
            int r = idx >> 2, ch = idx & 3;
            cp16(smem_u32(st + arr * GTILE_E + r * GSTR + ch * 8),
                 bases[arr] + (size_t)r * K + k0 + ch * 8);
        }
        CP_COMMIT();
    };

    const uint32_t a_off =
        (uint32_t)((wm * 64 + (lane & 15)) * GSTR + (lane >> 4) * 8) * 2;
    const uint32_t b_off =
        (uint32_t)((wn * 64 + ((lane >> 4) & 1) * 8 + (lane & 7)) * GSTR +
                   ((lane >> 3) & 1) * 8) * 2;

    float acc[4][8][4];
#pragma unroll
    for (int i = 0; i < 4; i++)
#pragma unroll
        for (int j = 0; j < 8; j++)
#pragma unroll
            for (int e = 0; e < 4; e++) acc[i][j][e] = 0.f;

    issue(0);
    issue(1);

    for (int s = 0; s < nsteps; s++) {
        if (s + 1 < nsteps) { CP_WAIT1(); } else { CP_WAIT0(); }
        __syncthreads();

        const uint32_t st = smb_u + (uint32_t)((s & 1) * PSTAGE_E) * 2;
        const uint32_t uAh = st;
        const uint32_t uBh = st + GTILE_E * 2;

#pragma unroll
        for (int ks = 0; ks < 2; ks++) {
            const uint32_t kso = (uint32_t)(ks * 16) * 2;
            uint32_t ah[4][4];
#pragma unroll
            for (int mt = 0; mt < 4; mt++) {
                const uint32_t ro = (uint32_t)(mt * 16 * GSTR) * 2;
                ldsm_x4(ah[mt], uAh + a_off + ro + kso);
            }
#pragma unroll
            for (int pp = 0; pp < 2; pp++) {
                uint32_t bh[2][4];
#pragma unroll
                for (int q2 = 0; q2 < 2; q2++) {
                    const uint32_t ro =
                        (uint32_t)(((pp * 2 + q2) * 16) * GSTR) * 2;
                    ldsm_x4(bh[q2], uBh + b_off + ro + kso);
                }
#pragma unroll
                for (int q2 = 0; q2 < 2; q2++) {
                    const int nt = (pp * 2 + q2) * 2;
#pragma unroll
                    for (int mt = 0; mt < 4; mt++) {
                        mma16816h(acc[mt][nt],     ah[mt], bh[q2][0], bh[q2][1]);
                        mma16816h(acc[mt][nt + 1], ah[mt], bh[q2][2], bh[q2][3]);
                    }
                }
            }
        }

        __syncthreads();
        if (s + 2 < nsteps) issue(s + 2);
    }

    // ---- epilogue --------------------------------------------------------
#pragma unroll
    for (int mt = 0; mt < 4; mt++) {
#pragma unroll
        for (int nt = 0; nt < 8; nt++) {
            const int m = m0 + wm * 64 + mt * 16 + g;
            const int n = n0 + wn * 64 + nt * 8 + t * 2;
            const float* c = acc[mt][nt];
            float2 bv = *(const float2*)(bias + n);
            if (MODE == 0) {
                *(float2*)(C + (size_t)m * N + n) =
                    make_float2(c[0] + bv.x, c[1] + bv.y);
                *(float2*)(C + (size_t)(m + 8) * N + n) =
                    make_float2(c[2] + bv.x, c[3] + bv.y);
            } else {
                const int which = n >> 10;
                const int h = (n >> 6) & 15;
                const int d = n & 63;
                const float sc = (which == 1) ? QSCALE : 1.0f;
                __half* dst = (which == 0) ? g_kh : (which == 1) ? g_qh : g_vh;
#pragma unroll
                for (int rr = 0; rr < 2; rr++) {
                    const int mm = m + rr * 8;
                    const int b = mm >> 11, s = mm & 2047;
                    const size_t off =
                        ((((size_t)b * H_ + h) * S_) + s) * D_ + d;
                    *(uint32_t*)(dst + off) =
                        pack_f16x2((c[rr * 2 + 0] + bv.x) * sc,
                                   (c[rr * 2 + 1] + bv.y) * sc);
                }
            }
        }
    }
}

// ---------------------------------------------------------------------------
// V transpose: [bh][s][d] -> [bh][d][s] (fp16)
// ---------------------------------------------------------------------------
__global__ __launch_bounds__(256) void vtrans_kernel() {
    __shared__ __half tile[64][72];
    const int tid = threadIdx.x;
    const int st = blockIdx.x;
    const int bh = blockIdx.y;

    const __half* src = g_vh + ((size_t)bh * S_ + st * 64) * D_;
    __half* dst = g_vth + (size_t)bh * D_ * S_ + st * 64;

#pragma unroll
    for (int c = 0; c < 8; c++) {
        int ci = tid + c * 256;
        int r = ci >> 5, ch = ci & 31;
        *(uint32_t*)&tile[r][ch * 2] =
            *(const uint32_t*)(src + (size_t)r * D_ + ch * 2);
    }
    __syncthreads();
#pragma unroll
    for (int c = 0; c < 8; c++) {
        int ci = tid + c * 256;
        int d = ci >> 5, s2 = (ci & 31) * 2;
        __half2 o = __halves2half2(tile[s2][d], tile[s2 + 1][d]);
        *(uint32_t*)(dst + (size_t)d * S_ + s2) = *(uint32_t*)&o;
    }
}

// ---------------------------------------------------------------------------
// Tensor-core causal flash attention, pure fp16, half2 MUFU softmax.
// CTA = (q-tile 128, bh), 8 warps, 2-stage KV ring, 2 CTAs/SM.
// ---------------------------------------------------------------------------
constexpr int ASTR = 72;
constexpr int AQ_E = 128 * ASTR;
constexpr int AKT_E = 64 * ASTR;
constexpr int AKSTAGE_E = 2 * AKT_E;            // kh, vth
constexpr int ASMEM = (AQ_E + 2 * AKSTAGE_E) * 2;   // 55296 B

__global__ __launch_bounds__(256, 2) void attn_mma() {
    extern __shared__ __half sma[];
    const uint32_t sma_u = smem_u32(sma);
    const int tid = threadIdx.x;
    const int lane = tid & 31;
    const int w = tid >> 5;
    const int g = lane >> 2, t = lane & 3;
    const int qt = (S_ / 128 - 1) - blockIdx.x;
    const int bh = blockIdx.y;
    const int nkt = 2 * qt + 2;

    __half* QH = sma;
    const uint32_t KV0_u = sma_u + AQ_E * 2;

    {
        const __half* qsrc = g_qh + ((size_t)bh * S_ + qt * 128) * D_;
#pragma unroll
        for (int c = 0; c < 4; c++) {
            int ci = tid + c * 256;
            int r = ci >> 3, ch = ci & 7;
            cp16(smem_u32(sma + r * ASTR + ch * 8),
                 qsrc + (size_t)r * D_ + ch * 8);
        }
        CP_COMMIT();
    }

    auto issueKV = [&](int kt) {
        uint32_t st = KV0_u + (uint32_t)((kt & 1) * AKSTAGE_E) * 2;
        const __half* bases[2] = {
            g_kh + ((size_t)bh * S_ + kt * 64) * D_,
            g_vth + (size_t)bh * D_ * S_ + kt * 64 };
#pragma unroll
        for (int c = 0; c < 4; c++) {
            int ci = tid + c * 256;
            int arr = ci >> 9;
            int idx = ci & 511;
            int r = idx >> 3, ch = idx & 7;
            const size_t rs = (arr == 0) ? (size_t)D_ : (size_t)S_;
            cp16(st + (uint32_t)(arr * AKT_E + r * ASTR + ch * 8) * 2,
                 bases[arr] + (size_t)r * rs + ch * 8);
        }
        CP_COMMIT();
    };

    issueKV(0);
    CP_WAIT1();
    __syncthreads();

    uint32_t qfh[4][4];
#pragma unroll
    for (int ks = 0; ks < 4; ks++) {
        const int kb = ks * 16 + t * 2;
        const int r0 = (w * 16 + g) * ASTR;
        qfh[ks][0] = *(const uint32_t*)(QH + r0 + kb);
        qfh[ks][1] = *(const uint32_t*)(QH + r0 + 8 * ASTR + kb);
        qfh[ks][2] = *(const uint32_t*)(QH + r0 + kb + 8);
        qfh[ks][3] = *(const uint32_t*)(QH + r0 + 8 * ASTR + kb + 8);
    }

    const uint32_t bfrag_off =
        (uint32_t)((((lane >> 4) & 1) * 8 + (lane & 7)) * ASTR +
                   ((lane >> 3) & 1) * 8) * 2;

    float o[8][4];
#pragma unroll
    for (int nt = 0; nt < 8; nt++)
#pragma unroll
        for (int e = 0; e < 4; e++) o[nt][e] = 0.f;
    float m0 = -1e30f, m1 = -1e30f, l0 = 0.f, l1 = 0.f;

    const int row0 = qt * 128 + w * 16 + g;
    const int row1 = row0 + 8;

    for (int kt = 0; kt < nkt; kt++) {
        CP_WAIT0();
        __syncthreads();
        if (kt + 1 < nkt) issueKV(kt + 1);

        if (kt * 64 > qt * 128 + w * 16 + 15) continue;

        const uint32_t st = KV0_u + (uint32_t)((kt & 1) * AKSTAGE_E) * 2;
        const uint32_t uKH = st;
        const uint32_t uVH = st + AKT_E * 2;

        // ---- S = Qh @ Kh^T
        float sc[8][4];
#pragma unroll
        for (int nt = 0; nt < 8; nt++)
#pragma unroll
            for (int e = 0; e < 4; e++) sc[nt][e] = 0.f;

#pragma unroll
        for (int ks = 0; ks < 4; ks++) {
            const uint32_t kso = (uint32_t)(ks * 16) * 2;
            uint32_t kh4[4][4];
#pragma unroll
            for (int ntp = 0; ntp < 4; ntp++) {
                const uint32_t ro = (uint32_t)((ntp * 16) * ASTR) * 2;
                ldsm_x4(kh4[ntp], uKH + bfrag_off + ro + kso);
            }
#pragma unroll
            for (int ntp = 0; ntp < 4; ntp++) {
                mma16816h(sc[2 * ntp],     qfh[ks], kh4[ntp][0], kh4[ntp][1]);
                mma16816h(sc[2 * ntp + 1], qfh[ks], kh4[ntp][2], kh4[ntp][3]);
            }
        }

        // ---- causal mask
        if (kt >= 2 * qt) {
#pragma unroll
            for (int nt = 0; nt < 8; nt++) {
                const int c0 = kt * 64 + nt * 8 + 2 * t;
                if (c0 > row0)     sc[nt][0] = -1e30f;
                if (c0 + 1 > row0) sc[nt][1] = -1e30f;
                if (c0 > row1)     sc[nt][2] = -1e30f;
                if (c0 + 1 > row1) sc[nt][3] = -1e30f;
            }
        }

        // ---- online softmax: max in fp32, exp via ex2.approx.f16x2
        float mx0 = -1e30f, mx1 = -1e30f;
#pragma unroll
        for (int nt = 0; nt < 8; nt++) {
            mx0 = fmaxf(mx0, fmaxf(sc[nt][0], sc[nt][1]));
            mx1 = fmaxf(mx1, fmaxf(sc[nt][2], sc[nt][3]));
        }
        mx0 = fmaxf(mx0, __shfl_xor_sync(0xffffffffu, mx0, 1));
        mx0 = fmaxf(mx0, __shfl_xor_sync(0xffffffffu, mx0, 2));
        mx1 = fmaxf(mx1, __shfl_xor_sync(0xffffffffu, mx1, 1));
        mx1 = fmaxf(mx1, __shfl_xor_sync(0xffffffffu, mx1, 2));

        const float mn0 = fmaxf(m0, mx0), mn1 = fmaxf(m1, mx1);
        const float a0 = exp2p(m0 - mn0), a1 = exp2p(m1 - mn1);
        m0 = mn0; m1 = mn1;

        // exp of all 32 scores in half2 (results ARE the P fragments)
        uint32_t pe[8][2];
        float rs0 = 0.f, rs1 = 0.f;
#pragma unroll
        for (int nt = 0; nt < 8; nt++) {
            uint32_t e0 = h2exp2(pack_f16x2(sc[nt][0] - mn0, sc[nt][1] - mn0));
            uint32_t e1 = h2exp2(pack_f16x2(sc[nt][2] - mn1, sc[nt][3] - mn1));
            float2 f0 = __half22float2(*(__half2*)&e0);
            float2 f1 = __half22float2(*(__half2*)&e1);
            rs0 += f0.x + f0.y;
            rs1 += f1.x + f1.y;
            pe[nt][0] = e0;
            pe[nt][1] = e1;
        }
        rs0 += __shfl_xor_sync(0xffffffffu, rs0, 1);
        rs0 += __shfl_xor_sync(0xffffffffu, rs0, 2);
        rs1 += __shfl_xor_sync(0xffffffffu, rs1, 1);
        rs1 += __shfl_xor_sync(0xffffffffu, rs1, 2);
        l0 = l0 * a0 + rs0;
        l1 = l1 * a1 + rs1;

#pragma unroll
        for (int nt = 0; nt < 8; nt++) {
            o[nt][0] *= a0; o[nt][1] *= a0;
            o[nt][2] *= a1; o[nt][3] *= a1;
        }

        // ---- O += P @ V  (P fragments = pe, already packed fp16)
#pragma unroll
        for (int ks = 0; ks < 4; ks++) {
            const uint32_t kso = (uint32_t)(ks * 16) * 2;
            const uint32_t pf[4] = { pe[2 * ks][0], pe[2 * ks][1],
                                     pe[2 * ks + 1][0], pe[2 * ks + 1][1] };
            uint32_t vh4[4][4];
#pragma unroll
            for (int ntp = 0; ntp < 4; ntp++) {
                const uint32_t ro = (uint32_t)((ntp * 16) * ASTR) * 2;
                ldsm_x4(vh4[ntp], uVH + bfrag_off + ro + kso);
            }
#pragma unroll
            for (int ntp = 0; ntp < 4; ntp++) {
                mma16816h(o[2 * ntp],     pf, vh4[ntp][0], vh4[ntp][1]);
                mma16816h(o[2 * ntp + 1], pf, vh4[ntp][2], vh4[ntp][3]);
            }
        }
    }

    // ---- epilogue: y = O / l as fp16 [b][s][h*64+d]
    const float inv0 = 1.0f / l0, inv1 = 1.0f / l1;
    const int b = bh >> 4, h = bh & 15;
#pragma unroll
    for (int nt = 0; nt < 8; nt++) {
        const int e = h * 64 + nt * 8 + 2 * t;
        {
            const size_t off = ((size_t)b * S_ + row0) * E_ + e;
            *(uint32_t*)(g_yh + off) =
                pack_f16x2(o[nt][0] * inv0, o[nt][1] * inv0);
        }
        {
            const size_t off = ((size_t)b * S_ + row1) * E_ + e;
            *(uint32_t*)(g_yh + off) =
                pack_f16x2(o[nt][2] * inv1, o[nt][3] * inv1);
        }
    }
}

// ---------------------------------------------------------------------------
// Launch
// ---------------------------------------------------------------------------
extern "C" void kernel_launch(void* const* d_in, const int* in_sizes, int n_in,
                              void* d_out, int out_size)
{
    const float* x      = (const float*)d_in[0];
    const float* W_kqv  = (const float*)d_in[1];
    const float* b_kqv  = (const float*)d_in[2];
    const float* W_proj = (const float*)d_in[3];
    const float* b_proj = (const float*)d_in[4];
    float* out = (float*)d_out;

    void *xh, *wkh, *wph, *yh;
    cudaGetSymbolAddress(&xh, g_xh);
    cudaGetSymbolAddress(&wkh, g_wkh);
    cudaGetSymbolAddress(&wph, g_wph);
    cudaGetSymbolAddress(&yh, g_yh);

    cudaFuncSetAttribute(gemm_h1<0>, cudaFuncAttributeMaxDynamicSharedMemorySize, PSMEM);
    cudaFuncSetAttribute(gemm_h1<1>, cudaFuncAttributeMaxDynamicSharedMemorySize, PSMEM);
    cudaFuncSetAttribute(attn_mma,  cudaFuncAttributeMaxDynamicSharedMemorySize, ASMEM);

    // 0) conversions (single launch)
    convAll_kernel<<<(CN_TOT + 255) / 256, 256>>>(x, W_kqv, W_proj);

    // 1) QKV projection -> q/k/v (fp16, natural)
    gemm_h1<1><<<dim3(NKQV / 128, M_ / 128), 128, PSMEM>>>(
        (const __half*)xh, (const __half*)wkh, b_kqv, nullptr, NKQV, E_);

    // 2) V transpose [bh][s][d] -> [bh][d][s]
    vtrans_kernel<<<dim3(S_ / 64, B_ * H_), 256>>>();

    // 3) Tensor-core causal flash attention -> y fp16
    attn_mma<<<dim3(S_ / 128, B_ * H_), 256, ASMEM>>>();

    // 4) Output projection -> d_out
    gemm_h1<0><<<dim3(E_ / 128, M_ / 128), 128, PSMEM>>>(
        (const __half*)yh, (const __half*)wph, b_proj, out, E_, E_);
}